// round 2
// baseline (speedup 1.0000x reference)
#include <cuda_runtime.h>
#include <cstdint>

// Gate_33930241638461: fused router GEMM + gumbel top-2 + softmax
//   logits[T,E] = x[T,D] @ W[E,D]^T + b[E]
//   scores = logits + gumbel(u);  top2 -> indices, softmax(top2) -> weights
// Output layout (f32): [ indices (T*2) | logits (T*E) | weights (T*2) ]

constexpr int D  = 1024;
constexpr int E  = 64;
constexpr int BM = 128;
constexpr int BK = 32;
constexpr float EPSF = 1e-9f;

__global__ void __launch_bounds__(256, 2)
gate_kernel(const float* __restrict__ x,
            const float* __restrict__ W,
            const float* __restrict__ bvec,
            const float* __restrict__ u,
            float* __restrict__ out_idx,
            float* __restrict__ out_logits,
            float* __restrict__ out_w)
{
    __shared__ union SMem {
        struct {
            float As[BK][BM];   // x tile, transposed (k-major rows)
            float Ws[BK][E];    // W tile, transposed
        } g;
        float Sc[BM][E + 1];    // scores staging (stride 65 -> conflict-free)
    } sm;

    const int tid = threadIdx.x;
    const int m0  = blockIdx.x * BM;
    const int tx  = tid & 15;   // N direction: 16 threads * 4 cols
    const int ty  = tid >> 4;   // M direction: 16 threads * 8 rows

    float acc[8][4];
    #pragma unroll
    for (int i = 0; i < 8; i++)
        #pragma unroll
        for (int j = 0; j < 4; j++) acc[i][j] = 0.0f;

    for (int k0 = 0; k0 < D; k0 += BK) {
        // ---- load x tile [BM, BK] -> As[k][m] (transposed store) ----
        #pragma unroll
        for (int j = 0; j < 4; j++) {
            const int f   = tid + j * 256;       // 0..1023 float4 slots
            const int row = f >> 3;              // 8 float4 per row
            const int q   = f & 7;
            const float4 v = *reinterpret_cast<const float4*>(
                &x[(size_t)(m0 + row) * D + k0 + q * 4]);
            sm.g.As[q * 4 + 0][row] = v.x;
            sm.g.As[q * 4 + 1][row] = v.y;
            sm.g.As[q * 4 + 2][row] = v.z;
            sm.g.As[q * 4 + 3][row] = v.w;
        }
        // ---- load W tile [E, BK] -> Ws[k][e] ----
        #pragma unroll
        for (int j = 0; j < 2; j++) {
            const int f = tid + j * 256;         // 0..511 float4 slots
            const int e = f >> 3;
            const int q = f & 7;
            const float4 v = *reinterpret_cast<const float4*>(
                &W[(size_t)e * D + k0 + q * 4]);
            sm.g.Ws[q * 4 + 0][e] = v.x;
            sm.g.Ws[q * 4 + 1][e] = v.y;
            sm.g.Ws[q * 4 + 2][e] = v.z;
            sm.g.Ws[q * 4 + 3][e] = v.w;
        }
        __syncthreads();

        #pragma unroll
        for (int kk = 0; kk < BK; kk++) {
            const float4 a0 = *reinterpret_cast<const float4*>(&sm.g.As[kk][ty * 8]);
            const float4 a1 = *reinterpret_cast<const float4*>(&sm.g.As[kk][ty * 8 + 4]);
            const float4 bb = *reinterpret_cast<const float4*>(&sm.g.Ws[kk][tx * 4]);
            const float a[8] = {a0.x, a0.y, a0.z, a0.w, a1.x, a1.y, a1.z, a1.w};
            const float bf[4] = {bb.x, bb.y, bb.z, bb.w};
            #pragma unroll
            for (int i = 0; i < 8; i++)
                #pragma unroll
                for (int j = 0; j < 4; j++)
                    acc[i][j] = fmaf(a[i], bf[j], acc[i][j]);
        }
        __syncthreads();
    }

    // ---- bias add, write logits to gmem, stage scores(logits) to smem ----
    float bias[4];
    #pragma unroll
    for (int j = 0; j < 4; j++) bias[j] = __ldg(&bvec[tx * 4 + j]);

    #pragma unroll
    for (int i = 0; i < 8; i++) {
        const int row = ty * 8 + i;
        float4 v;
        v.x = acc[i][0] + bias[0];
        v.y = acc[i][1] + bias[1];
        v.z = acc[i][2] + bias[2];
        v.w = acc[i][3] + bias[3];
        *reinterpret_cast<float4*>(&out_logits[(size_t)(m0 + row) * E + tx * 4]) = v;
        sm.Sc[row][tx * 4 + 0] = v.x;
        sm.Sc[row][tx * 4 + 1] = v.y;
        sm.Sc[row][tx * 4 + 2] = v.z;
        sm.Sc[row][tx * 4 + 3] = v.w;
    }
    __syncthreads();

    // ---- epilogue: warp-per-row gumbel + top-2 + softmax ----
    const int warp = tid >> 5;
    const int lane = tid & 31;

    for (int r = warp; r < BM; r += 8) {
        const size_t t = (size_t)(m0 + r);
        const float ua = u[t * E + lane];
        const float ub = u[t * E + lane + 32];
        const float ga = -__logf(-__logf(ua + EPSF) + EPSF);
        const float gb = -__logf(-__logf(ub + EPSF) + EPSF);
        float sa = sm.Sc[r][lane]      + ga;
        float sb = sm.Sc[r][lane + 32] + gb;
        int ia = lane, ib = lane + 32;

        // local top-2 (lower index wins ties -> matches jax.lax.top_k)
        float m1, m2; int i1, i2;
        if (sb > sa) { m1 = sb; i1 = ib; m2 = sa; i2 = ia; }
        else         { m1 = sa; i1 = ia; m2 = sb; i2 = ib; }

        #pragma unroll
        for (int off = 16; off > 0; off >>= 1) {
            const float om1 = __shfl_xor_sync(0xffffffffu, m1, off);
            const int   oi1 = __shfl_xor_sync(0xffffffffu, i1, off);
            const float om2 = __shfl_xor_sync(0xffffffffu, m2, off);
            const int   oi2 = __shfl_xor_sync(0xffffffffu, i2, off);
            const bool mine_first = (m1 > om1) || (m1 == om1 && i1 < oi1);
            float n1, n2; int ni1, ni2;
            if (mine_first) {
                n1 = m1; ni1 = i1;
                const bool c = (om1 > m2) || (om1 == m2 && oi1 < i2);
                if (c) { n2 = om1; ni2 = oi1; } else { n2 = m2; ni2 = i2; }
            } else {
                n1 = om1; ni1 = oi1;
                const bool c = (m1 > om2) || (m1 == om2 && i1 < oi2);
                if (c) { n2 = m1; ni2 = i1; } else { n2 = om2; ni2 = oi2; }
            }
            m1 = n1; i1 = ni1; m2 = n2; i2 = ni2;
        }

        if (lane == 0) {
            const float e2 = __expf(m2 - m1);      // m1 >= m2
            const float inv = 1.0f / (1.0f + e2);
            out_idx[t * 2 + 0] = (float)i1;
            out_idx[t * 2 + 1] = (float)i2;
            out_w[t * 2 + 0]   = inv;
            out_w[t * 2 + 1]   = e2 * inv;
        }
    }
}

extern "C" void kernel_launch(void* const* d_in, const int* in_sizes, int n_in,
                              void* d_out, int out_size)
{
    const float* x = (const float*)d_in[0];
    const float* W = (const float*)d_in[1];
    const float* b = (const float*)d_in[2];
    const float* u = (const float*)d_in[3];

    const int T = in_sizes[3] / E;   // u is [T, E]

    float* out        = (float*)d_out;
    float* out_idx    = out;                         // [T, 2]
    float* out_logits = out + (size_t)T * 2;         // [T, E]
    float* out_w      = out_logits + (size_t)T * E;  // [T, 2]

    const int grid = (T + BM - 1) / BM;
    gate_kernel<<<grid, 256>>>(x, W, b, u, out_idx, out_logits, out_w);
}

// round 6
// speedup vs baseline: 2.1952x; 2.1952x over previous
#include <cuda_runtime.h>
#include <cuda_bf16.h>
#include <cstdint>

// Gate_33930241638461 — HMMA (mma.sync) bf16 split-precision router
//   logits[T,64] = x[T,1024] @ W[64,1024]^T + b
//   scores = logits + gumbel(u); top2 -> indices; softmax(top2) -> weights
// Output (f32): [ indices (T*2) | logits (T*64) | weights (T*2) ]

constexpr int D  = 1024;
constexpr int E  = 64;
constexpr int BM = 128;
constexpr int BK = 64;               // K-chunk
constexpr int NCHUNK = D / BK;       // 16
constexpr int WROW = 144;            // padded W smem row bytes (72 bf16) -> conflict-free B LDS
constexpr float EPSF = 1e-9f;

// Pre-split W (bf16 hi/lo); L2-resident, read by all CTAs.
__device__ __nv_bfloat16 g_Whi[E * D];
__device__ __nv_bfloat16 g_Wlo[E * D];

__global__ void prep_kernel(const float* __restrict__ W) {
    const int base = blockIdx.x * 1024 + threadIdx.x;
    #pragma unroll
    for (int k = 0; k < 4; k++) {
        const int i = base + k * 256;
        const float w = W[i];
        const __nv_bfloat16 hi = __float2bfloat16(w);
        g_Whi[i] = hi;
        g_Wlo[i] = __float2bfloat16(w - __bfloat162float(hi));
    }
}

__device__ __forceinline__ void mma16816(float* c, const uint32_t* a, uint32_t b0, uint32_t b1) {
    asm volatile(
        "mma.sync.aligned.m16n8k16.row.col.f32.bf16.bf16.f32 "
        "{%0,%1,%2,%3},{%4,%5,%6,%7},{%8,%9},{%0,%1,%2,%3};"
        : "+f"(c[0]), "+f"(c[1]), "+f"(c[2]), "+f"(c[3])
        : "r"(a[0]), "r"(a[1]), "r"(a[2]), "r"(a[3]), "r"(b0), "r"(b1));
}

// pack two floats to bf16x2 (hi), return residuals for lo pass
__device__ __forceinline__ uint32_t pack_hi(float2 v, float2& res) {
    __nv_bfloat162 h = __float22bfloat162_rn(v);
    res.x = v.x - __bfloat162float(h.x);
    res.y = v.y - __bfloat162float(h.y);
    return *reinterpret_cast<uint32_t*>(&h);
}
__device__ __forceinline__ uint32_t pack_lo(float2 r) {
    __nv_bfloat162 l = __float22bfloat162_rn(r);
    return *reinterpret_cast<uint32_t*>(&l);
}

__global__ void __launch_bounds__(256, 2)
gate_kernel(const float* __restrict__ x,
            const float* __restrict__ bvec,
            const float* __restrict__ u,
            float* __restrict__ out_idx,
            float* __restrict__ out_logits,
            float* __restrict__ out_w)
{
    __shared__ union SMem {
        struct { unsigned char hi[E * WROW]; unsigned char lo[E * WROW]; } w;  // 18432 B
        float Sc[BM * 66];                                                      // 33792 B
    } sm;
    __shared__ float s_bias[E];

    const int tid  = threadIdx.x;
    const int wid  = tid >> 5;
    const int lane = tid & 31;
    const int g    = lane >> 2;      // groupID
    const int t    = lane & 3;       // thread-in-group
    const int m0   = blockIdx.x * BM;
    const int warpRow = m0 + wid * 16;

    if (tid < E) s_bias[tid] = bvec[tid];

    // A fragment gmem base for this lane: row (warpRow+g), col 2t.
    const float* xA = x + (size_t)(warpRow + g) * D + 2 * t;
    // quad offsets: q0:(r,c) q1:(r+8,c) q2:(r,c+8) q3:(r+8,c+8)
    const size_t qoff[4] = { 0, (size_t)8 * D, 8, (size_t)8 * D + 8 };

    float acc[8][4];
    #pragma unroll
    for (int n = 0; n < 8; n++)
        #pragma unroll
        for (int j = 0; j < 4; j++) acc[n][j] = 0.0f;

    // preload chunk 0 A fragments (fp32)
    float2 acur[4][4];
    #pragma unroll
    for (int ks = 0; ks < 4; ks++)
        #pragma unroll
        for (int q = 0; q < 4; q++)
            acur[ks][q] = *reinterpret_cast<const float2*>(xA + ks * 16 + qoff[q]);

    for (int c = 0; c < NCHUNK; c++) {
        // convert current A to bf16 hi/lo fragments (frees acur for prefetch)
        uint32_t ahc[4][4], alc[4][4];
        #pragma unroll
        for (int ks = 0; ks < 4; ks++)
            #pragma unroll
            for (int q = 0; q < 4; q++) {
                float2 r;
                ahc[ks][q] = pack_hi(acur[ks][q], r);
                alc[ks][q] = pack_lo(r);
            }

        // prefetch next chunk A (in flight during W load + compute)
        if (c + 1 < NCHUNK) {
            const float* xn = xA + (c + 1) * BK;
            #pragma unroll
            for (int ks = 0; ks < 4; ks++)
                #pragma unroll
                for (int q = 0; q < 4; q++)
                    acur[ks][q] = *reinterpret_cast<const float2*>(xn + ks * 16 + qoff[q]);
        }

        __syncthreads();   // previous chunk's W fully consumed

        // cooperative W tile load: [64 rows][64 bf16] -> padded 144B rows
        #pragma unroll
        for (int j = 0; j < 2; j++) {
            const int f = tid + j * 256;       // 512 uint4 slots per split
            const int r = f >> 3;
            const int q = f & 7;
            const size_t src = (size_t)r * D + c * BK + q * 8;
            *reinterpret_cast<uint4*>(sm.w.hi + r * WROW + q * 16) =
                *reinterpret_cast<const uint4*>(&g_Whi[src]);
            *reinterpret_cast<uint4*>(sm.w.lo + r * WROW + q * 16) =
                *reinterpret_cast<const uint4*>(&g_Wlo[src]);
        }
        __syncthreads();

        // compute: 4 k-steps x 8 n-tiles x 3 split passes
        #pragma unroll
        for (int ks = 0; ks < 4; ks++) {
            #pragma unroll
            for (int nt = 0; nt < 8; nt++) {
                const int boff = (nt * 8 + g) * WROW + ks * 32 + t * 4;
                const uint32_t bh0 = *reinterpret_cast<const uint32_t*>(sm.w.hi + boff);
                const uint32_t bh1 = *reinterpret_cast<const uint32_t*>(sm.w.hi + boff + 16);
                const uint32_t bl0 = *reinterpret_cast<const uint32_t*>(sm.w.lo + boff);
                const uint32_t bl1 = *reinterpret_cast<const uint32_t*>(sm.w.lo + boff + 16);
                mma16816(acc[nt], ahc[ks], bh0, bh1);   // hi*hi
                mma16816(acc[nt], ahc[ks], bl0, bl1);   // hi*lo
                mma16816(acc[nt], alc[ks], bh0, bh1);   // lo*hi
            }
        }
    }

    __syncthreads();   // W smem dead; alias as Sc

    // stage scores (+bias) to smem: rows wid*16+g and +8
    const int wr0 = wid * 16 + g;
    #pragma unroll
    for (int nt = 0; nt < 8; nt++) {
        const int col = nt * 8 + 2 * t;
        const float bx = s_bias[col], by = s_bias[col + 1];
        *reinterpret_cast<float2*>(&sm.Sc[wr0 * 66 + col]) =
            make_float2(acc[nt][0] + bx, acc[nt][1] + by);
        *reinterpret_cast<float2*>(&sm.Sc[(wr0 + 8) * 66 + col]) =
            make_float2(acc[nt][2] + bx, acc[nt][3] + by);
    }
    __syncthreads();

    // epilogue: coalesced logits write + gumbel top-2 + softmax (warp per row)
    for (int r = wid; r < BM; r += 8) {
        const size_t tk = (size_t)(m0 + r);

        const float l0 = sm.Sc[r * 66 + lane * 2];
        const float l1 = sm.Sc[r * 66 + lane * 2 + 1];
        *reinterpret_cast<float2*>(&out_logits[tk * E + lane * 2]) = make_float2(l0, l1);

        const float ua = u[tk * E + lane];
        const float ub = u[tk * E + lane + 32];
        const float ga = -__logf(-__logf(ua + EPSF) + EPSF);
        const float gb = -__logf(-__logf(ub + EPSF) + EPSF);
        float sa = sm.Sc[r * 66 + lane]      + ga;
        float sb = sm.Sc[r * 66 + lane + 32] + gb;
        int ia = lane, ib = lane + 32;

        float m1, m2; int i1, i2;
        if (sb > sa) { m1 = sb; i1 = ib; m2 = sa; i2 = ia; }
        else         { m1 = sa; i1 = ia; m2 = sb; i2 = ib; }

        #pragma unroll
        for (int off = 16; off > 0; off >>= 1) {
            const float om1 = __shfl_xor_sync(0xffffffffu, m1, off);
            const int   oi1 = __shfl_xor_sync(0xffffffffu, i1, off);
            const float om2 = __shfl_xor_sync(0xffffffffu, m2, off);
            const int   oi2 = __shfl_xor_sync(0xffffffffu, i2, off);
            const bool mine_first = (m1 > om1) || (m1 == om1 && i1 < oi1);
            float n1, n2; int ni1, ni2;
            if (mine_first) {
                n1 = m1; ni1 = i1;
                const bool cgt = (om1 > m2) || (om1 == m2 && oi1 < i2);
                if (cgt) { n2 = om1; ni2 = oi1; } else { n2 = m2; ni2 = i2; }
            } else {
                n1 = om1; ni1 = oi1;
                const bool cgt = (m1 > om2) || (m1 == om2 && i1 < oi2);
                if (cgt) { n2 = m1; ni2 = i1; } else { n2 = om2; ni2 = oi2; }
            }
            m1 = n1; i1 = ni1; m2 = n2; i2 = ni2;
        }

        if (lane == 0) {
            const float e2  = __expf(m2 - m1);   // m1 >= m2
            const float inv = 1.0f / (1.0f + e2);
            out_idx[tk * 2 + 0] = (float)i1;
            out_idx[tk * 2 + 1] = (float)i2;
            out_w[tk * 2 + 0]   = inv;
            out_w[tk * 2 + 1]   = e2 * inv;
        }
    }
}

extern "C" void kernel_launch(void* const* d_in, const int* in_sizes, int n_in,
                              void* d_out, int out_size)
{
    const float* x = (const float*)d_in[0];
    const float* W = (const float*)d_in[1];
    const float* b = (const float*)d_in[2];
    const float* u = (const float*)d_in[3];

    const int T = in_sizes[3] / E;   // u is [T, E]

    float* out        = (float*)d_out;
    float* out_idx    = out;                         // [T, 2]
    float* out_logits = out + (size_t)T * 2;         // [T, E]
    float* out_w      = out_logits + (size_t)T * E;  // [T, 2]

    prep_kernel<<<E * D / 1024, 256>>>(W);           // 64 blocks
    gate_kernel<<<T / BM, 256>>>(x, b, u, out_idx, out_logits, out_w);
}

// round 7
// speedup vs baseline: 2.7183x; 1.2383x over previous
#include <cuda_runtime.h>
#include <cuda_bf16.h>
#include <cstdint>

// Gate_33930241638461 — HMMA bf16 4-pass split router, ldmatrix + cp.async ring
//   logits[T,64] = x[T,1024] @ W[64,1024]^T + b
//   scores = logits + gumbel(u); top2 -> indices; softmax(top2) -> weights
// Output (f32): [ indices (T*2) | logits (T*64) | weights (T*2) ]

constexpr int D  = 1024;
constexpr int E  = 64;
constexpr int BM = 128;
constexpr int BK = 64;                    // K-chunk
constexpr int NCHUNK = D / BK;            // 16
constexpr int WROW = 144;                 // padded smem row bytes (72 bf16)
constexpr int SPLIT_BYTES = E * WROW;     // 9216
constexpr int BUF_BYTES   = 2 * SPLIT_BYTES;  // hi+lo, 18432
constexpr int SMEM_DYN    = 3 * BUF_BYTES;    // 3-stage ring, 55296
constexpr float EPSF = 1e-9f;

// Pre-split W (bf16 hi/lo); L2-resident, read by all CTAs.
__device__ __nv_bfloat16 g_Whi[E * D];
__device__ __nv_bfloat16 g_Wlo[E * D];

__global__ void prep_kernel(const float* __restrict__ W) {
    const int base = blockIdx.x * 1024 + threadIdx.x;
    #pragma unroll
    for (int k = 0; k < 4; k++) {
        const int i = base + k * 256;
        const float w = W[i];
        const __nv_bfloat16 hi = __float2bfloat16(w);
        g_Whi[i] = hi;
        g_Wlo[i] = __float2bfloat16(w - __bfloat162float(hi));
    }
}

// ---------- helpers ----------
__device__ __forceinline__ uint32_t smem_u32(const void* p) {
    uint32_t a;
    asm("{ .reg .u64 t; cvta.to.shared.u64 t, %1; cvt.u32.u64 %0, t; }" : "=r"(a) : "l"(p));
    return a;
}
__device__ __forceinline__ void mma16816(float* c, const uint32_t* a, uint32_t b0, uint32_t b1) {
    asm volatile(
        "mma.sync.aligned.m16n8k16.row.col.f32.bf16.bf16.f32 "
        "{%0,%1,%2,%3},{%4,%5,%6,%7},{%8,%9},{%0,%1,%2,%3};"
        : "+f"(c[0]), "+f"(c[1]), "+f"(c[2]), "+f"(c[3])
        : "r"(a[0]), "r"(a[1]), "r"(a[2]), "r"(a[3]), "r"(b0), "r"(b1));
}
__device__ __forceinline__ void ldm4(uint32_t* r, uint32_t addr) {
    asm volatile("ldmatrix.sync.aligned.m8n8.x4.shared.b16 {%0,%1,%2,%3}, [%4];"
                 : "=r"(r[0]), "=r"(r[1]), "=r"(r[2]), "=r"(r[3]) : "r"(addr));
}
__device__ __forceinline__ void cp_async16(uint32_t dst, const void* src) {
    asm volatile("cp.async.cg.shared.global [%0], [%1], 16;" :: "r"(dst), "l"(src));
}
#define CP_COMMIT() asm volatile("cp.async.commit_group;" ::: "memory")
template <int N> __device__ __forceinline__ void cp_wait() {
    asm volatile("cp.async.wait_group %0;" :: "n"(N) : "memory");
}
__device__ __forceinline__ uint32_t pack_hi(float2 v, float2& res) {
    __nv_bfloat162 h = __float22bfloat162_rn(v);
    res.x = v.x - __bfloat162float(h.x);
    res.y = v.y - __bfloat162float(h.y);
    return *reinterpret_cast<uint32_t*>(&h);
}
__device__ __forceinline__ uint32_t pack_lo(float2 r) {
    __nv_bfloat162 l = __float22bfloat162_rn(r);
    return *reinterpret_cast<uint32_t*>(&l);
}

__global__ void __launch_bounds__(256, 2)
gate_kernel(const float* __restrict__ x,
            const float* __restrict__ bvec,
            const float* __restrict__ u,
            float* __restrict__ out_idx,
            float* __restrict__ out_logits,
            float* __restrict__ out_w)
{
    extern __shared__ char dsm[];          // W ring [3][hi|lo]; epilogue aliases Sc
    __shared__ float s_bias[E];

    const int tid  = threadIdx.x;
    const int wid  = tid >> 5;
    const int lane = tid & 31;
    const int g    = lane >> 2;            // groupID
    const int t    = lane & 3;             // thread-in-group
    const int m0   = blockIdx.x * BM;
    const int warpRow = m0 + wid * 16;
    const uint32_t dsmB = smem_u32(dsm);

    if (tid < E) s_bias[tid] = bvec[tid];

    // ldmatrix per-lane row base: matrix mIdx = lane>>3 -> (nt_local = mIdx>>1, khalf = mIdx&1)
    const int mIdx = lane >> 3;
    const int mr   = lane & 7;
    const uint32_t lmBase = (uint32_t)(((mIdx >> 1) * 8 + mr) * WROW + (mIdx & 1) * 16);

    // W chunk issue (cp.async): [64 rows][64 bf16] per split into padded rows
    auto issueW = [&](int c) {
        const uint32_t base = dsmB + (c % 3) * BUF_BYTES;
        #pragma unroll
        for (int s = 0; s < 2; s++) {
            const __nv_bfloat16* src = s ? g_Wlo : g_Whi;
            #pragma unroll
            for (int j = 0; j < 2; j++) {
                const int f = tid + j * 256;
                const int r = f >> 3;
                const int q = f & 7;
                cp_async16(base + s * SPLIT_BYTES + r * WROW + q * 16,
                           src + (size_t)r * D + c * BK + q * 8);
            }
        }
        CP_COMMIT();
    };

    // A fragment gmem base: row (warpRow+g), col 2t; quad offsets per m16n8k16 A layout
    const float* xA = x + (size_t)(warpRow + g) * D + 2 * t;
    const size_t qoff[4] = { 0, (size_t)8 * D, 8, (size_t)8 * D + 8 };

    float acc[8][4];
    #pragma unroll
    for (int n = 0; n < 8; n++)
        #pragma unroll
        for (int j = 0; j < 4; j++) acc[n][j] = 0.0f;

    // preload chunk 0 A (fp32) and issue W chunk 0
    float2 acur[4][4];
    #pragma unroll
    for (int ks = 0; ks < 4; ks++)
        #pragma unroll
        for (int q = 0; q < 4; q++)
            acur[ks][q] = *reinterpret_cast<const float2*>(xA + ks * 16 + qoff[q]);
    issueW(0);

    for (int c = 0; c < NCHUNK; c++) {
        if (c + 1 < NCHUNK) issueW(c + 1);
        if (c + 1 < NCHUNK) cp_wait<1>(); else cp_wait<0>();
        __syncthreads();                      // W[c] ready; ring buf (c+1)%3 free

        // convert A chunk c to bf16 hi/lo fragments
        uint32_t ahc[4][4], alc[4][4];
        #pragma unroll
        for (int ks = 0; ks < 4; ks++)
            #pragma unroll
            for (int q = 0; q < 4; q++) {
                float2 r;
                ahc[ks][q] = pack_hi(acur[ks][q], r);
                alc[ks][q] = pack_lo(r);
            }

        // prefetch A chunk c+1 (LDGs fly under compute)
        if (c + 1 < NCHUNK) {
            const float* xn = xA + (c + 1) * BK;
            #pragma unroll
            for (int ks = 0; ks < 4; ks++)
                #pragma unroll
                for (int q = 0; q < 4; q++)
                    acur[ks][q] = *reinterpret_cast<const float2*>(xn + ks * 16 + qoff[q]);
        }

        // compute: 4 k-steps x 4 nt-pairs; ldmatrix.x4 loads b0,b1 for two n-tiles
        const uint32_t wb = dsmB + (c % 3) * BUF_BYTES;
        #pragma unroll
        for (int ks = 0; ks < 4; ks++) {
            #pragma unroll
            for (int ntp = 0; ntp < 4; ntp++) {
                uint32_t h[4], l[4];
                const uint32_t a0 = wb + lmBase + ntp * (16 * WROW) + ks * 32;
                ldm4(h, a0);
                ldm4(l, a0 + SPLIT_BYTES);
                float* c0 = acc[2 * ntp];
                float* c1 = acc[2 * ntp + 1];
                mma16816(c0, ahc[ks], h[0], h[1]);   // hi*hi
                mma16816(c1, ahc[ks], h[2], h[3]);
                mma16816(c0, ahc[ks], l[0], l[1]);   // hi*lo
                mma16816(c1, ahc[ks], l[2], l[3]);
                mma16816(c0, alc[ks], h[0], h[1]);   // lo*hi
                mma16816(c1, alc[ks], h[2], h[3]);
                mma16816(c0, alc[ks], l[0], l[1]);   // lo*lo
                mma16816(c1, alc[ks], l[2], l[3]);
            }
        }
    }

    __syncthreads();                          // W ring dead; alias as Sc[128][66]
    float* Sc = reinterpret_cast<float*>(dsm);

    // stage scores (+bias): rows wid*16+g and +8
    const int wr0 = wid * 16 + g;
    #pragma unroll
    for (int nt = 0; nt < 8; nt++) {
        const int col = nt * 8 + 2 * t;
        const float bx = s_bias[col], by = s_bias[col + 1];
        *reinterpret_cast<float2*>(&Sc[wr0 * 66 + col]) =
            make_float2(acc[nt][0] + bx, acc[nt][1] + by);
        *reinterpret_cast<float2*>(&Sc[(wr0 + 8) * 66 + col]) =
            make_float2(acc[nt][2] + bx, acc[nt][3] + by);
    }
    __syncthreads();

    // epilogue: coalesced logits write + gumbel top-2 + softmax (warp per row)
    for (int r = wid; r < BM; r += 8) {
        const size_t tk = (size_t)(m0 + r);

        const float l0 = Sc[r * 66 + lane * 2];
        const float l1 = Sc[r * 66 + lane * 2 + 1];
        *reinterpret_cast<float2*>(&out_logits[tk * E + lane * 2]) = make_float2(l0, l1);

        const float ua = u[tk * E + lane];
        const float ub = u[tk * E + lane + 32];
        const float ga = -__logf(-__logf(ua + EPSF) + EPSF);
        const float gb = -__logf(-__logf(ub + EPSF) + EPSF);
        float sa = Sc[r * 66 + lane]      + ga;
        float sb = Sc[r * 66 + lane + 32] + gb;
        int ia = lane, ib = lane + 32;

        float m1, m2; int i1, i2;
        if (sb > sa) { m1 = sb; i1 = ib; m2 = sa; i2 = ia; }
        else         { m1 = sa; i1 = ia; m2 = sb; i2 = ib; }

        #pragma unroll
        for (int off = 16; off > 0; off >>= 1) {
            const float om1 = __shfl_xor_sync(0xffffffffu, m1, off);
            const int   oi1 = __shfl_xor_sync(0xffffffffu, i1, off);
            const float om2 = __shfl_xor_sync(0xffffffffu, m2, off);
            const int   oi2 = __shfl_xor_sync(0xffffffffu, i2, off);
            const bool mine_first = (m1 > om1) || (m1 == om1 && i1 < oi1);
            float n1, n2; int ni1, ni2;
            if (mine_first) {
                n1 = m1; ni1 = i1;
                const bool cgt = (om1 > m2) || (om1 == m2 && oi1 < i2);
                if (cgt) { n2 = om1; ni2 = oi1; } else { n2 = m2; ni2 = i2; }
            } else {
                n1 = om1; ni1 = oi1;
                const bool cgt = (m1 > om2) || (m1 == om2 && i1 < oi2);
                if (cgt) { n2 = m1; ni2 = i1; } else { n2 = om2; ni2 = oi2; }
            }
            m1 = n1; i1 = ni1; m2 = n2; i2 = ni2;
        }

        if (lane == 0) {
            const float e2  = __expf(m2 - m1);   // m1 >= m2
            const float inv = 1.0f / (1.0f + e2);
            out_idx[tk * 2 + 0] = (float)i1;
            out_idx[tk * 2 + 1] = (float)i2;
            out_w[tk * 2 + 0]   = inv;
            out_w[tk * 2 + 1]   = e2 * inv;
        }
    }
}

extern "C" void kernel_launch(void* const* d_in, const int* in_sizes, int n_in,
                              void* d_out, int out_size)
{
    const float* x = (const float*)d_in[0];
    const float* W = (const float*)d_in[1];
    const float* b = (const float*)d_in[2];
    const float* u = (const float*)d_in[3];

    const int T = in_sizes[3] / E;   // u is [T, E]

    float* out        = (float*)d_out;
    float* out_idx    = out;                         // [T, 2]
    float* out_logits = out + (size_t)T * 2;         // [T, E]
    float* out_w      = out_logits + (size_t)T * E;  // [T, 2]

    cudaFuncSetAttribute(gate_kernel, cudaFuncAttributeMaxDynamicSharedMemorySize, SMEM_DYN);

    prep_kernel<<<E * D / 1024, 256>>>(W);           // 64 blocks
    gate_kernel<<<T / BM, 256, SMEM_DYN>>>(x, b, u, out_idx, out_logits, out_w);
}

// round 12
// speedup vs baseline: 3.2739x; 1.2044x over previous
#include <cuda_runtime.h>
#include <cuda_bf16.h>
#include <cstdint>

// Gate_33930241638461 — HMMA bf16 4-pass split router
//   ldmatrix B-frags + cp.async 3-stage W ring + in-register epilogue
//   logits[T,64] = x[T,1024] @ W[64,1024]^T + b
//   scores = logits + gumbel(u); top2 -> indices; softmax(top2) -> weights
// Output (f32): [ indices (T*2) | logits (T*64) | weights (T*2) ]

constexpr int D  = 1024;
constexpr int E  = 64;
constexpr int BM = 128;
constexpr int BK = 64;                    // K-chunk
constexpr int NCHUNK = D / BK;            // 16
constexpr int WROW = 144;                 // padded smem row bytes (72 bf16)
constexpr int SPLIT_BYTES = E * WROW;     // 9216
constexpr int BUF_BYTES   = 2 * SPLIT_BYTES;  // hi+lo, 18432
constexpr int SMEM_DYN    = 3 * BUF_BYTES;    // 3-stage ring, 55296
constexpr float EPSF = 1e-9f;

// Pre-split W (bf16 hi/lo); L2-resident, read by all CTAs.
__device__ __nv_bfloat16 g_Whi[E * D];
__device__ __nv_bfloat16 g_Wlo[E * D];

__global__ void prep_kernel(const float* __restrict__ W) {
    const int base = blockIdx.x * 1024 + threadIdx.x;
    #pragma unroll
    for (int k = 0; k < 4; k++) {
        const int i = base + k * 256;
        const float w = W[i];
        const __nv_bfloat16 hi = __float2bfloat16(w);
        g_Whi[i] = hi;
        g_Wlo[i] = __float2bfloat16(w - __bfloat162float(hi));
    }
}

// ---------- helpers ----------
__device__ __forceinline__ uint32_t smem_u32(const void* p) {
    uint32_t a;
    asm("{ .reg .u64 t; cvta.to.shared.u64 t, %1; cvt.u32.u64 %0, t; }" : "=r"(a) : "l"(p));
    return a;
}
__device__ __forceinline__ void mma16816(float* c, const uint32_t* a, uint32_t b0, uint32_t b1) {
    asm volatile(
        "mma.sync.aligned.m16n8k16.row.col.f32.bf16.bf16.f32 "
        "{%0,%1,%2,%3},{%4,%5,%6,%7},{%8,%9},{%0,%1,%2,%3};"
        : "+f"(c[0]), "+f"(c[1]), "+f"(c[2]), "+f"(c[3])
        : "r"(a[0]), "r"(a[1]), "r"(a[2]), "r"(a[3]), "r"(b0), "r"(b1));
}
__device__ __forceinline__ void ldm4(uint32_t* r, uint32_t addr) {
    asm volatile("ldmatrix.sync.aligned.m8n8.x4.shared.b16 {%0,%1,%2,%3}, [%4];"
                 : "=r"(r[0]), "=r"(r[1]), "=r"(r[2]), "=r"(r[3]) : "r"(addr));
}
__device__ __forceinline__ void cp_async16(uint32_t dst, const void* src) {
    asm volatile("cp.async.cg.shared.global [%0], [%1], 16;" :: "r"(dst), "l"(src));
}
#define CP_COMMIT() asm volatile("cp.async.commit_group;" ::: "memory")
template <int N> __device__ __forceinline__ void cp_wait() {
    asm volatile("cp.async.wait_group %0;" :: "n"(N) : "memory");
}
__device__ __forceinline__ uint32_t pack_hi(float2 v, float2& res) {
    __nv_bfloat162 h = __float22bfloat162_rn(v);
    res.x = v.x - __bfloat162float(h.x);
    res.y = v.y - __bfloat162float(h.y);
    return *reinterpret_cast<uint32_t*>(&h);
}
__device__ __forceinline__ uint32_t pack_lo(float2 r) {
    __nv_bfloat162 l = __float22bfloat162_rn(r);
    return *reinterpret_cast<uint32_t*>(&l);
}

__global__ void __launch_bounds__(256, 2)
gate_kernel(const float* __restrict__ x,
            const float* __restrict__ bvec,
            const float* __restrict__ u,
            float* __restrict__ out_idx,
            float* __restrict__ out_logits,
            float* __restrict__ out_w)
{
    extern __shared__ char dsm[];          // W ring [3][hi|lo]
    __shared__ float s_bias[E];

    const int tid  = threadIdx.x;
    const int wid  = tid >> 5;
    const int lane = tid & 31;
    const int g    = lane >> 2;            // groupID
    const int t    = lane & 3;             // thread-in-group
    const int m0   = blockIdx.x * BM;
    const int warpRow = m0 + wid * 16;
    const uint32_t dsmB = smem_u32(dsm);

    if (tid < E) s_bias[tid] = bvec[tid];

    // ldmatrix per-lane row base: matrix mIdx = lane>>3 -> (nt_local = mIdx>>1, khalf = mIdx&1)
    const int mIdx = lane >> 3;
    const int mr   = lane & 7;
    const uint32_t lmBase = (uint32_t)(((mIdx >> 1) * 8 + mr) * WROW + (mIdx & 1) * 16);

    // W chunk issue (cp.async): [64 rows][64 bf16] per split into padded rows
    auto issueW = [&](int c) {
        const uint32_t base = dsmB + (c % 3) * BUF_BYTES;
        #pragma unroll
        for (int s = 0; s < 2; s++) {
            const __nv_bfloat16* src = s ? g_Wlo : g_Whi;
            #pragma unroll
            for (int j = 0; j < 2; j++) {
                const int f = tid + j * 256;
                const int r = f >> 3;
                const int q = f & 7;
                cp_async16(base + s * SPLIT_BYTES + r * WROW + q * 16,
                           src + (size_t)r * D + c * BK + q * 8);
            }
        }
        CP_COMMIT();
    };

    // A fragment gmem base: row (warpRow+g), col 2t; quad offsets per m16n8k16 A layout
    const float* xA = x + (size_t)(warpRow + g) * D + 2 * t;
    const size_t qoff[4] = { 0, (size_t)8 * D, 8, (size_t)8 * D + 8 };

    float acc[8][4];
    #pragma unroll
    for (int n = 0; n < 8; n++)
        #pragma unroll
        for (int j = 0; j < 4; j++) acc[n][j] = 0.0f;

    // preload chunk 0 A (fp32) and issue W chunk 0
    float2 acur[4][4];
    #pragma unroll
    for (int ks = 0; ks < 4; ks++)
        #pragma unroll
        for (int q = 0; q < 4; q++)
            acur[ks][q] = *reinterpret_cast<const float2*>(xA + ks * 16 + qoff[q]);
    issueW(0);

    for (int c = 0; c < NCHUNK; c++) {
        if (c + 1 < NCHUNK) { issueW(c + 1); cp_wait<1>(); }
        else                { cp_wait<0>(); }
        __syncthreads();                      // W[c] ready; ring buf (c+1)%3 free

        const uint32_t wb = dsmB + (c % 3) * BUF_BYTES;
        const float* xn = xA + (c + 1) * BK;
        const bool pf = (c + 1 < NCHUNK);

        #pragma unroll
        for (int ks = 0; ks < 4; ks++) {
            // convert this ks fragment to bf16 hi/lo (frees acur[ks] for prefetch)
            uint32_t ahc[4], alc[4];
            #pragma unroll
            for (int q = 0; q < 4; q++) {
                float2 r;
                ahc[q] = pack_hi(acur[ks][q], r);
                alc[q] = pack_lo(r);
            }
            // prefetch next chunk's ks fragment (LDGs fly under MMAs)
            if (pf) {
                #pragma unroll
                for (int q = 0; q < 4; q++)
                    acur[ks][q] = *reinterpret_cast<const float2*>(xn + ks * 16 + qoff[q]);
            }
            // 4 nt-pairs x 4 split passes
            #pragma unroll
            for (int ntp = 0; ntp < 4; ntp++) {
                uint32_t h[4], l[4];
                const uint32_t a0 = wb + lmBase + ntp * (16 * WROW) + ks * 32;
                ldm4(h, a0);
                ldm4(l, a0 + SPLIT_BYTES);
                float* c0 = acc[2 * ntp];
                float* c1 = acc[2 * ntp + 1];
                mma16816(c0, ahc, h[0], h[1]);   // hi*hi
                mma16816(c1, ahc, h[2], h[3]);
                mma16816(c0, ahc, l[0], l[1]);   // hi*lo
                mma16816(c1, ahc, l[2], l[3]);
                mma16816(c0, alc, h[0], h[1]);   // lo*hi
                mma16816(c1, alc, h[2], h[3]);
                mma16816(c0, alc, l[0], l[1]);   // lo*lo
                mma16816(c1, alc, l[2], l[3]);
            }
        }
    }

    // ---- in-register epilogue: no barriers, no smem staging ----
    // Lane (g,t) holds rows r0=warpRow+g and r0+8; cols {8nt+2t, 8nt+2t+1}.
    #pragma unroll
    for (int half = 0; half < 2; half++) {
        const size_t tk = (size_t)(warpRow + g + half * 8);

        float m1 = -1e30f, m2 = -1e30f;
        int   i1 = 0,      i2 = 0;

        #pragma unroll
        for (int nt = 0; nt < 8; nt++) {
            const int col = nt * 8 + 2 * t;
            const float l0 = acc[nt][half * 2 + 0] + s_bias[col];
            const float l1 = acc[nt][half * 2 + 1] + s_bias[col + 1];
            *reinterpret_cast<float2*>(&out_logits[tk * E + col]) = make_float2(l0, l1);

            const float2 uv = *reinterpret_cast<const float2*>(&u[tk * E + col]);
            const float s0 = l0 + (-__logf(-__logf(uv.x + EPSF) + EPSF));
            const float s1 = l1 + (-__logf(-__logf(uv.y + EPSF) + EPSF));

            // ascending col scan; strict > keeps lowest col on ties
            if (s0 > m1)      { m2 = m1; i2 = i1; m1 = s0; i1 = col; }
            else if (s0 > m2) { m2 = s0; i2 = col; }
            if (s1 > m1)      { m2 = m1; i2 = i1; m1 = s1; i1 = col + 1; }
            else if (s1 > m2) { m2 = s1; i2 = col + 1; }
        }

        // quad merge (lanes differing in bits 0-1 share the row)
        #pragma unroll
        for (int off = 1; off <= 2; off <<= 1) {
            const float om1 = __shfl_xor_sync(0xffffffffu, m1, off);
            const int   oi1 = __shfl_xor_sync(0xffffffffu, i1, off);
            const float om2 = __shfl_xor_sync(0xffffffffu, m2, off);
            const int   oi2 = __shfl_xor_sync(0xffffffffu, i2, off);
            const bool mine_first = (m1 > om1) || (m1 == om1 && i1 < oi1);
            float n1, n2; int ni1, ni2;
            if (mine_first) {
                n1 = m1; ni1 = i1;
                const bool cgt = (om1 > m2) || (om1 == m2 && oi1 < i2);
                if (cgt) { n2 = om1; ni2 = oi1; } else { n2 = m2; ni2 = i2; }
            } else {
                n1 = om1; ni1 = oi1;
                const bool cgt = (m1 > om2) || (m1 == om2 && i1 < oi2);
                if (cgt) { n2 = m1; ni2 = i1; } else { n2 = om2; ni2 = oi2; }
            }
            m1 = n1; i1 = ni1; m2 = n2; i2 = ni2;
        }

        if (t == 0) {
            const float e2  = __expf(m2 - m1);   // m1 >= m2
            const float inv = 1.0f / (1.0f + e2);
            *reinterpret_cast<float2*>(&out_idx[tk * 2]) = make_float2((float)i1, (float)i2);
            *reinterpret_cast<float2*>(&out_w[tk * 2])   = make_float2(inv, e2 * inv);
        }
    }
}

extern "C" void kernel_launch(void* const* d_in, const int* in_sizes, int n_in,
                              void* d_out, int out_size)
{
    const float* x = (const float*)d_in[0];
    const float* W = (const float*)d_in[1];
    const float* b = (const float*)d_in[2];
    const float* u = (const float*)d_in[3];

    const int T = in_sizes[3] / E;   // u is [T, E]

    float* out        = (float*)d_out;
    float* out_idx    = out;                         // [T, 2]
    float* out_logits = out + (size_t)T * 2;         // [T, E]
    float* out_w      = out_logits + (size_t)T * E;  // [T, 2]

    cudaFuncSetAttribute(gate_kernel, cudaFuncAttributeMaxDynamicSharedMemorySize, SMEM_DYN);

    prep_kernel<<<E * D / 1024, 256>>>(W);           // 64 blocks
    gate_kernel<<<T / BM, 256, SMEM_DYN>>>(x, b, u, out_idx, out_logits, out_w);
}

// round 13
// speedup vs baseline: 3.7518x; 1.1460x over previous
#include <cuda_runtime.h>
#include <cuda_bf16.h>
#include <cstdint>

// Gate_33930241638461 — HMMA bf16 3-pass split router
//   ldmatrix B-frags + cp.async 3-stage W ring + in-register epilogue
//   logits[T,64] = x[T,1024] @ W[64,1024]^T + b
//   scores = logits + gumbel(u); top2 -> indices; softmax(top2) -> weights
// Output (f32): [ indices (T*2) | logits (T*64) | weights (T*2) ]

constexpr int D  = 1024;
constexpr int E  = 64;
constexpr int BM = 128;
constexpr int BK = 64;                    // K-chunk
constexpr int NCHUNK = D / BK;            // 16
constexpr int WROW = 144;                 // padded smem row bytes (72 bf16)
constexpr int SPLIT_BYTES = E * WROW;     // 9216
constexpr int BUF_BYTES   = 2 * SPLIT_BYTES;  // hi+lo, 18432
constexpr int SMEM_DYN    = 3 * BUF_BYTES;    // 3-stage ring, 55296
constexpr float EPSF = 1e-9f;

// Pre-split W (bf16 hi/lo); L2-resident, read by all CTAs.
__device__ __nv_bfloat16 g_Whi[E * D];
__device__ __nv_bfloat16 g_Wlo[E * D];

__global__ void prep_kernel(const float* __restrict__ W) {
    const int base = blockIdx.x * 1024 + threadIdx.x;
    #pragma unroll
    for (int k = 0; k < 4; k++) {
        const int i = base + k * 256;
        const float w = W[i];
        const __nv_bfloat16 hi = __float2bfloat16(w);
        g_Whi[i] = hi;
        g_Wlo[i] = __float2bfloat16(w - __bfloat162float(hi));
    }
}

// ---------- helpers ----------
__device__ __forceinline__ uint32_t smem_u32(const void* p) {
    uint32_t a;
    asm("{ .reg .u64 t; cvta.to.shared.u64 t, %1; cvt.u32.u64 %0, t; }" : "=r"(a) : "l"(p));
    return a;
}
__device__ __forceinline__ void mma16816(float* c, const uint32_t* a, uint32_t b0, uint32_t b1) {
    asm volatile(
        "mma.sync.aligned.m16n8k16.row.col.f32.bf16.bf16.f32 "
        "{%0,%1,%2,%3},{%4,%5,%6,%7},{%8,%9},{%0,%1,%2,%3};"
        : "+f"(c[0]), "+f"(c[1]), "+f"(c[2]), "+f"(c[3])
        : "r"(a[0]), "r"(a[1]), "r"(a[2]), "r"(a[3]), "r"(b0), "r"(b1));
}
__device__ __forceinline__ void ldm4(uint32_t* r, uint32_t addr) {
    asm volatile("ldmatrix.sync.aligned.m8n8.x4.shared.b16 {%0,%1,%2,%3}, [%4];"
                 : "=r"(r[0]), "=r"(r[1]), "=r"(r[2]), "=r"(r[3]) : "r"(addr));
}
__device__ __forceinline__ void cp_async16(uint32_t dst, const void* src) {
    asm volatile("cp.async.cg.shared.global [%0], [%1], 16;" :: "r"(dst), "l"(src));
}
#define CP_COMMIT() asm volatile("cp.async.commit_group;" ::: "memory")
template <int N> __device__ __forceinline__ void cp_wait() {
    asm volatile("cp.async.wait_group %0;" :: "n"(N) : "memory");
}
__device__ __forceinline__ uint32_t pack_hi(float2 v, float2& res) {
    __nv_bfloat162 h = __float22bfloat162_rn(v);
    res.x = v.x - __bfloat162float(h.x);
    res.y = v.y - __bfloat162float(h.y);
    return *reinterpret_cast<uint32_t*>(&h);
}
__device__ __forceinline__ uint32_t pack_lo(float2 r) {
    __nv_bfloat162 l = __float22bfloat162_rn(r);
    return *reinterpret_cast<uint32_t*>(&l);
}

__global__ void __launch_bounds__(256, 2)
gate_kernel(const float* __restrict__ x,
            const float* __restrict__ bvec,
            const float* __restrict__ u,
            float* __restrict__ out_idx,
            float* __restrict__ out_logits,
            float* __restrict__ out_w)
{
    extern __shared__ char dsm[];          // W ring [3][hi|lo]
    __shared__ float s_bias[E];

    const int tid  = threadIdx.x;
    const int wid  = tid >> 5;
    const int lane = tid & 31;
    const int g    = lane >> 2;            // groupID
    const int t    = lane & 3;             // thread-in-group
    const int m0   = blockIdx.x * BM;
    const int warpRow = m0 + wid * 16;
    const uint32_t dsmB = smem_u32(dsm);

    if (tid < E) s_bias[tid] = bvec[tid];

    // ldmatrix per-lane row base: matrix mIdx = lane>>3 -> (nt_local = mIdx>>1, khalf = mIdx&1)
    const int mIdx = lane >> 3;
    const int mr   = lane & 7;
    const uint32_t lmBase = (uint32_t)(((mIdx >> 1) * 8 + mr) * WROW + (mIdx & 1) * 16);

    // W chunk issue (cp.async): [64 rows][64 bf16] per split into padded rows
    auto issueW = [&](int c) {
        const uint32_t base = dsmB + (c % 3) * BUF_BYTES;
        #pragma unroll
        for (int s = 0; s < 2; s++) {
            const __nv_bfloat16* src = s ? g_Wlo : g_Whi;
            #pragma unroll
            for (int j = 0; j < 2; j++) {
                const int f = tid + j * 256;
                const int r = f >> 3;
                const int q = f & 7;
                cp_async16(base + s * SPLIT_BYTES + r * WROW + q * 16,
                           src + (size_t)r * D + c * BK + q * 8);
            }
        }
        CP_COMMIT();
    };

    // A fragment gmem base: row (warpRow+g), col 2t; quad offsets per m16n8k16 A layout
    const float* xA = x + (size_t)(warpRow + g) * D + 2 * t;
    const size_t qoff[4] = { 0, (size_t)8 * D, 8, (size_t)8 * D + 8 };

    float acc[8][4];
    #pragma unroll
    for (int n = 0; n < 8; n++)
        #pragma unroll
        for (int j = 0; j < 4; j++) acc[n][j] = 0.0f;

    // preload chunk 0 A (fp32) and issue W chunk 0
    float2 acur[4][4];
    #pragma unroll
    for (int ks = 0; ks < 4; ks++)
        #pragma unroll
        for (int q = 0; q < 4; q++)
            acur[ks][q] = *reinterpret_cast<const float2*>(xA + ks * 16 + qoff[q]);
    issueW(0);

    for (int c = 0; c < NCHUNK; c++) {
        if (c + 1 < NCHUNK) { issueW(c + 1); cp_wait<1>(); }
        else                { cp_wait<0>(); }
        __syncthreads();                      // W[c] ready; ring buf (c+1)%3 free

        const uint32_t wb = dsmB + (c % 3) * BUF_BYTES;
        const float* xn = xA + (c + 1) * BK;
        const bool pf = (c + 1 < NCHUNK);

        #pragma unroll
        for (int ks = 0; ks < 4; ks++) {
            // convert this ks fragment to bf16 hi/lo (frees acur[ks] for prefetch)
            uint32_t ahc[4], alc[4];
            #pragma unroll
            for (int q = 0; q < 4; q++) {
                float2 r;
                ahc[q] = pack_hi(acur[ks][q], r);
                alc[q] = pack_lo(r);
            }
            // prefetch next chunk's ks fragment (LDGs fly under MMAs)
            if (pf) {
                #pragma unroll
                for (int q = 0; q < 4; q++)
                    acur[ks][q] = *reinterpret_cast<const float2*>(xn + ks * 16 + qoff[q]);
            }
            // 4 nt-pairs x 3 split passes (per-acc order: hihi, hilo, lohi — matches R5 bits)
            #pragma unroll
            for (int ntp = 0; ntp < 4; ntp++) {
                uint32_t h[4], l[4];
                const uint32_t a0 = wb + lmBase + ntp * (16 * WROW) + ks * 32;
                ldm4(h, a0);
                ldm4(l, a0 + SPLIT_BYTES);
                float* c0 = acc[2 * ntp];
                float* c1 = acc[2 * ntp + 1];
                mma16816(c0, ahc, h[0], h[1]);   // hi*hi
                mma16816(c1, ahc, h[2], h[3]);
                mma16816(c0, ahc, l[0], l[1]);   // hi*lo
                mma16816(c1, ahc, l[2], l[3]);
                mma16816(c0, alc, h[0], h[1]);   // lo*hi
                mma16816(c1, alc, h[2], h[3]);
            }
        }
    }

    // ---- in-register epilogue: no barriers, no smem staging ----
    // Lane (g,t) holds rows r0=warpRow+g and r0+8; cols {8nt+2t, 8nt+2t+1}.
    #pragma unroll
    for (int half = 0; half < 2; half++) {
        const size_t tk = (size_t)(warpRow + g + half * 8);

        float m1 = -1e30f, m2 = -1e30f;
        int   i1 = 0,      i2 = 0;

        #pragma unroll
        for (int nt = 0; nt < 8; nt++) {
            const int col = nt * 8 + 2 * t;
            const float l0 = acc[nt][half * 2 + 0] + s_bias[col];
            const float l1 = acc[nt][half * 2 + 1] + s_bias[col + 1];
            *reinterpret_cast<float2*>(&out_logits[tk * E + col]) = make_float2(l0, l1);

            const float2 uv = *reinterpret_cast<const float2*>(&u[tk * E + col]);
            const float s0 = l0 + (-__logf(-__logf(uv.x + EPSF) + EPSF));
            const float s1 = l1 + (-__logf(-__logf(uv.y + EPSF) + EPSF));

            // ascending col scan; strict > keeps lowest col on ties
            if (s0 > m1)      { m2 = m1; i2 = i1; m1 = s0; i1 = col; }
            else if (s0 > m2) { m2 = s0; i2 = col; }
            if (s1 > m1)      { m2 = m1; i2 = i1; m1 = s1; i1 = col + 1; }
            else if (s1 > m2) { m2 = s1; i2 = col + 1; }
        }

        // quad merge (lanes differing in bits 0-1 share the row)
        #pragma unroll
        for (int off = 1; off <= 2; off <<= 1) {
            const float om1 = __shfl_xor_sync(0xffffffffu, m1, off);
            const int   oi1 = __shfl_xor_sync(0xffffffffu, i1, off);
            const float om2 = __shfl_xor_sync(0xffffffffu, m2, off);
            const int   oi2 = __shfl_xor_sync(0xffffffffu, i2, off);
            const bool mine_first = (m1 > om1) || (m1 == om1 && i1 < oi1);
            float n1, n2; int ni1, ni2;
            if (mine_first) {
                n1 = m1; ni1 = i1;
                const bool cgt = (om1 > m2) || (om1 == m2 && oi1 < i2);
                if (cgt) { n2 = om1; ni2 = oi1; } else { n2 = m2; ni2 = i2; }
            } else {
                n1 = om1; ni1 = oi1;
                const bool cgt = (m1 > om2) || (m1 == om2 && i1 < oi2);
                if (cgt) { n2 = m1; ni2 = i1; } else { n2 = om2; ni2 = oi2; }
            }
            m1 = n1; i1 = ni1; m2 = n2; i2 = ni2;
        }

        if (t == 0) {
            const float e2  = __expf(m2 - m1);   // m1 >= m2
            const float inv = 1.0f / (1.0f + e2);
            *reinterpret_cast<float2*>(&out_idx[tk * 2]) = make_float2((float)i1, (float)i2);
            *reinterpret_cast<float2*>(&out_w[tk * 2])   = make_float2(inv, e2 * inv);
        }
    }
}

extern "C" void kernel_launch(void* const* d_in, const int* in_sizes, int n_in,
                              void* d_out, int out_size)
{
    const float* x = (const float*)d_in[0];
    const float* W = (const float*)d_in[1];
    const float* b = (const float*)d_in[2];
    const float* u = (const float*)d_in[3];

    const int T = in_sizes[3] / E;   // u is [T, E]

    float* out        = (float*)d_out;
    float* out_idx    = out;                         // [T, 2]
    float* out_logits = out + (size_t)T * 2;         // [T, E]
    float* out_w      = out_logits + (size_t)T * E;  // [T, 2]

    cudaFuncSetAttribute(gate_kernel, cudaFuncAttributeMaxDynamicSharedMemorySize, SMEM_DYN);

    prep_kernel<<<E * D / 1024, 256>>>(W);           // 64 blocks
    gate_kernel<<<T / BM, 256, SMEM_DYN>>>(x, b, u, out_idx, out_logits, out_w);
}